// round 1
// baseline (speedup 1.0000x reference)
#include <cuda_runtime.h>
#include <math.h>

#define T_STEPS 1024
#define NCTA 128
#define RS_STRIDE 1028   // 1024 + 4 pad to kill LDS bank conflicts

// -------- scratch (static device globals: allocation-free) --------
__device__ float g_xproj[(size_t)16384 * 4096];       // 256 MB  [m=t*16+b][4096]
__device__ float g_hs[(size_t)16 * 1024 * 1024];      // 64 MB   [b][t][h]
__device__ float g_hglob[1024 * 16];                  // h_t, layout [k][b]
__device__ unsigned int g_bar_count;
__device__ volatile unsigned int g_bar_gen;

// -------- software grid barrier (all NCTA CTAs co-resident) --------
__device__ __forceinline__ void grid_barrier() {
    __syncthreads();
    if (threadIdx.x == 0) {
        __threadfence();
        unsigned int gen = g_bar_gen;
        unsigned int t = atomicAdd(&g_bar_count, 1u);
        if (t == NCTA - 1) {
            g_bar_count = 0u;
            __threadfence();
            g_bar_gen = gen + 1u;
        } else {
            while (g_bar_gen == gen) { __nanosleep(32); }
            __threadfence();
        }
    }
    __syncthreads();
}

// ===================================================================
// Phase A: x_proj[m][g] = sum_d A[m][d] * W[g][d] + bias[g]
// A row m -> (b = m&15, t = m>>4) at b*1048576 + t*1024 (works for both
// input_seq [B][T][D] and hs [B][T][H] since D == H == 1024).
// M=16384, N=4096, K=1024. 128x128 tile, 8x8 per thread, BK=16.
// ===================================================================
__global__ __launch_bounds__(256) void sgemm_xproj(
    const float* __restrict__ Ain,   // nullptr => use g_hs
    const float* __restrict__ Wl,    // [4096][1024]
    const float* __restrict__ bias)  // [4096]
{
    const float* A = Ain ? Ain : (const float*)g_hs;
    __shared__ float As[16][128];
    __shared__ float Bs[16][128];
    int tid = threadIdx.x;
    int n0 = blockIdx.x * 128;
    int m0 = blockIdx.y * 128;
    int tx = tid & 15, ty = tid >> 4;
    int lrow = tid >> 2;          // 0..63
    int lk = (tid & 3) * 4;       // 0,4,8,12

    float acc[8][8];
#pragma unroll
    for (int i = 0; i < 8; i++)
#pragma unroll
        for (int j = 0; j < 8; j++) acc[i][j] = 0.f;

    for (int k0 = 0; k0 < 1024; k0 += 16) {
#pragma unroll
        for (int rr = 0; rr < 2; rr++) {
            int row = lrow + rr * 64;
            int m = m0 + row;
            const float* ap = A + (size_t)(m & 15) * 1048576 + (size_t)(m >> 4) * 1024 + k0 + lk;
            float4 av = *(const float4*)ap;
            As[lk + 0][row] = av.x; As[lk + 1][row] = av.y;
            As[lk + 2][row] = av.z; As[lk + 3][row] = av.w;
            const float* wp = Wl + (size_t)(n0 + row) * 1024 + k0 + lk;
            float4 wv = *(const float4*)wp;
            Bs[lk + 0][row] = wv.x; Bs[lk + 1][row] = wv.y;
            Bs[lk + 2][row] = wv.z; Bs[lk + 3][row] = wv.w;
        }
        __syncthreads();
#pragma unroll
        for (int k = 0; k < 16; k++) {
            float a[8], bb[8];
            *(float4*)&a[0] = *(const float4*)&As[k][ty * 8];
            *(float4*)&a[4] = *(const float4*)&As[k][ty * 8 + 4];
            *(float4*)&bb[0] = *(const float4*)&Bs[k][tx * 8];
            *(float4*)&bb[4] = *(const float4*)&Bs[k][tx * 8 + 4];
#pragma unroll
            for (int i = 0; i < 8; i++)
#pragma unroll
                for (int j = 0; j < 8; j++)
                    acc[i][j] += a[i] * bb[j];
        }
        __syncthreads();
    }

#pragma unroll
    for (int i = 0; i < 8; i++) {
        int m = m0 + ty * 8 + i;
        float* cp = g_xproj + (size_t)m * 4096 + n0 + tx * 8;
#pragma unroll
        for (int j = 0; j < 8; j += 4) {
            float4 o;
            o.x = acc[i][j + 0] + bias[n0 + tx * 8 + j + 0];
            o.y = acc[i][j + 1] + bias[n0 + tx * 8 + j + 1];
            o.z = acc[i][j + 2] + bias[n0 + tx * 8 + j + 2];
            o.w = acc[i][j + 3] + bias[n0 + tx * 8 + j + 3];
            *(float4*)(cp + j) = o;
        }
    }
}

// ===================================================================
// Phase B: persistent sLSTM recurrence. 128 CTAs; CTA j owns h-units
// [8j, 8j+8) i.e. gate rows {g*1024 + 8j + u : g in 0..3, u in 0..7}.
// R slice (32x1024 fp32) resident in SMEM; h broadcast via g_hglob.
// SMEM: Rs 128.5KB + h 64KB + partials 16KB = 208.5KB -> 1 CTA/SM.
// ===================================================================
__global__ __launch_bounds__(256, 1) void slstm_rec(const float* __restrict__ Rl)
{
    extern __shared__ float smem[];
    float* sRs   = smem;                        // 32 * RS_STRIDE
    float* sH    = smem + 32 * RS_STRIDE;       // [1024][16]
    float* sPart = sH + 1024 * 16;              // [512][8]

    int tid = threadIdx.x;
    int u_base = blockIdx.x * 8;

    // stage R slice: local row r = gate*8 + u
#pragma unroll 1
    for (int r = 0; r < 32; r++) {
        int gate = r >> 3, uu = r & 7;
        const float* src = Rl + (size_t)(gate * 1024 + u_base + uu) * 1024 + tid * 4;
        float4 v = *(const float4*)src;
        float* dst = sRs + r * RS_STRIDE + tid * 4;
        dst[0] = v.x; dst[1] = v.y; dst[2] = v.z; dst[3] = v.w;
    }
    // h0 = 0
    for (int i = tid; i < 16384; i += 256) sH[i] = 0.f;

    // GEMM thread mapping: 8 k-splits x (8 u-positions x 4 b-groups)
    int ksplit = tid >> 5;
    int pos = tid & 31;
    int uu = pos >> 2;
    int b0 = (pos & 3) * 4;
    const float* rb0 = sRs + (0 * 8 + uu) * RS_STRIDE + ksplit * 128;
    const float* rb1 = sRs + (1 * 8 + uu) * RS_STRIDE + ksplit * 128;
    const float* rb2 = sRs + (2 * 8 + uu) * RS_STRIDE + ksplit * 128;
    const float* rb3 = sRs + (3 * 8 + uu) * RS_STRIDE + ksplit * 128;
    const float* hb = sH + ksplit * 128 * 16 + b0;

    // pointwise state (threads < 128): (b, u)
    int pu = tid & 7, pb = tid >> 3;
    float creg = 0.f, nreg = 1.f, mreg = 0.f;

    for (int t = 0; t < T_STEPS; t++) {
        if (t > 0) {
            // broadcast-read h_{t-1} from global into SMEM
            for (int i = tid * 4; i < 16384; i += 1024) {
                float4 v = *(const float4*)(g_hglob + i);
                *(float4*)(sH + i) = v;
            }
        }
        __syncthreads();

        float acc[4][4];
#pragma unroll
        for (int g = 0; g < 4; g++)
#pragma unroll
            for (int bb = 0; bb < 4; bb++) acc[g][bb] = 0.f;

#pragma unroll 2
        for (int kk = 0; kk < 128; kk += 4) {
            float4 rv0 = *(const float4*)(rb0 + kk);
            float4 rv1 = *(const float4*)(rb1 + kk);
            float4 rv2 = *(const float4*)(rb2 + kk);
            float4 rv3 = *(const float4*)(rb3 + kk);
            float4 hv0 = *(const float4*)(hb + (kk + 0) * 16);
            float4 hv1 = *(const float4*)(hb + (kk + 1) * 16);
            float4 hv2 = *(const float4*)(hb + (kk + 2) * 16);
            float4 hv3 = *(const float4*)(hb + (kk + 3) * 16);
#define DO_G(G, RV) \
            acc[G][0] += RV.x * hv0.x + RV.y * hv1.x + RV.z * hv2.x + RV.w * hv3.x; \
            acc[G][1] += RV.x * hv0.y + RV.y * hv1.y + RV.z * hv2.y + RV.w * hv3.y; \
            acc[G][2] += RV.x * hv0.z + RV.y * hv1.z + RV.z * hv2.z + RV.w * hv3.z; \
            acc[G][3] += RV.x * hv0.w + RV.y * hv1.w + RV.z * hv2.w + RV.w * hv3.w;
            DO_G(0, rv0) DO_G(1, rv1) DO_G(2, rv2) DO_G(3, rv3)
#undef DO_G
        }

#pragma unroll
        for (int g = 0; g < 4; g++)
#pragma unroll
            for (int bb = 0; bb < 4; bb++)
                sPart[((g * 8 + uu) * 16 + b0 + bb) * 8 + ksplit] = acc[g][bb];
        __syncthreads();

        if (tid < 128) {
            const float* xp = g_xproj + ((size_t)t * 16 + pb) * 4096 + u_base + pu;
            float pre[4];
#pragma unroll
            for (int g = 0; g < 4; g++) {
                float s = xp[g * 1024];
                const float* pp = sPart + ((g * 8 + pu) * 16 + pb) * 8;
#pragma unroll
                for (int ks = 0; ks < 8; ks++) s += pp[ks];
                pre[g] = s;
            }
            float z = tanhf(pre[0]);
            float o = 1.f / (1.f + expf(-pre[3]));
            float mn = fmaxf(pre[2] + mreg, pre[1]);
            float ip = expf(pre[1] - mn);
            float fp = expf(pre[2] + mreg - mn);
            creg = fp * creg + ip * z;
            nreg = fp * nreg + ip;
            mreg = mn;
            float h = o * (creg / nreg);
            g_hglob[(u_base + pu) * 16 + pb] = h;
            g_hs[(size_t)pb * 1048576 + (size_t)t * 1024 + u_base + pu] = h;
            __threadfence();
        }
        if (t + 1 < T_STEPS) grid_barrier();
    }
}

// ===================================================================
// Final: out[b][o] = sum_k h_last[b][k] * Wout[o][k] + bout[o]
// one warp per output column o.
// ===================================================================
__global__ __launch_bounds__(256) void final_out(
    const float* __restrict__ Wout, const float* __restrict__ bout,
    float* __restrict__ out)
{
    int o = (blockIdx.x * blockDim.x + threadIdx.x) >> 5;
    int lane = threadIdx.x & 31;
    const float* wr = Wout + (size_t)o * 1024;
    float acc[16];
#pragma unroll
    for (int b = 0; b < 16; b++) acc[b] = 0.f;
    for (int k = lane; k < 1024; k += 32) {
        float w = wr[k];
        const float4* hp = (const float4*)(g_hglob + k * 16);
        float4 h0 = hp[0], h1 = hp[1], h2 = hp[2], h3 = hp[3];
        acc[0]  += w * h0.x; acc[1]  += w * h0.y; acc[2]  += w * h0.z; acc[3]  += w * h0.w;
        acc[4]  += w * h1.x; acc[5]  += w * h1.y; acc[6]  += w * h1.z; acc[7]  += w * h1.w;
        acc[8]  += w * h2.x; acc[9]  += w * h2.y; acc[10] += w * h2.z; acc[11] += w * h2.w;
        acc[12] += w * h3.x; acc[13] += w * h3.y; acc[14] += w * h3.z; acc[15] += w * h3.w;
    }
#pragma unroll
    for (int b = 0; b < 16; b++) {
#pragma unroll
        for (int off = 16; off; off >>= 1)
            acc[b] += __shfl_down_sync(0xffffffffu, acc[b], off);
    }
    if (lane == 0) {
        float bo = bout[o];
#pragma unroll
        for (int b = 0; b < 16; b++)
            out[(size_t)b * 1024 + o] = acc[b] + bo;
    }
}

// ===================================================================
extern "C" void kernel_launch(void* const* d_in, const int* in_sizes, int n_in,
                              void* d_out, int out_size)
{
    const float* x    = (const float*)d_in[0];  // [16][1024][1024]
    const float* W    = (const float*)d_in[1];  // [2][4096][1024]
    const float* R    = (const float*)d_in[2];  // [2][4096][1024]
    const float* bias = (const float*)d_in[3];  // [2][4096]
    const float* Wout = (const float*)d_in[4];  // [1024][1024]
    const float* bout = (const float*)d_in[5];  // [1024]
    float* out = (float*)d_out;                 // [16][1024]

    const int REC_SMEM = (32 * RS_STRIDE + 1024 * 16 + 512 * 8) * 4; // 213504 B
    cudaFuncSetAttribute(slstm_rec, cudaFuncAttributeMaxDynamicSharedMemorySize, REC_SMEM);

    dim3 ggrid(32, 128);
    // layer 0
    sgemm_xproj<<<ggrid, 256>>>(x, W, bias);
    slstm_rec<<<NCTA, 256, REC_SMEM>>>(R);
    // layer 1
    sgemm_xproj<<<ggrid, 256>>>(nullptr, W + (size_t)4096 * 1024, bias + 4096);
    slstm_rec<<<NCTA, 256, REC_SMEM>>>(R + (size_t)4096 * 1024);
    // output projection
    final_out<<<128, 256>>>(Wout, bout, out);
}

// round 2
// speedup vs baseline: 1.3542x; 1.3542x over previous
#include <cuda_runtime.h>
#include <math.h>

#define T_STEPS 1024
#define NCTA 128
#define RS_STRIDE 1028   // 1024 + 4 pad (4 mod 32) to kill LDS bank conflicts

// -------- packed fp32x2 helpers (sm_103a FFMA2) --------
__device__ __forceinline__ void fma2(unsigned long long &d, unsigned long long a, unsigned long long b) {
    asm("fma.rn.f32x2 %0, %1, %2, %0;" : "+l"(d) : "l"(a), "l"(b));
}
__device__ __forceinline__ unsigned long long pack2(float x) {
    unsigned long long r; asm("mov.b64 %0, {%1, %1};" : "=l"(r) : "f"(x)); return r;
}
__device__ __forceinline__ float2 unpack2(unsigned long long v) {
    float2 r; asm("mov.b64 {%0, %1}, %2;" : "=f"(r.x), "=f"(r.y) : "l"(v)); return r;
}

// -------- scratch (static device globals: allocation-free) --------
__device__ float g_xproj[(size_t)16384 * 4096];       // 256 MB  [m=t*16+b][4096]
__device__ float g_hs[(size_t)16 * 1024 * 1024];      // 64 MB   [b][t][h]
__device__ float g_hglob[1024 * 16];                  // h_t, layout [k][b]
__device__ unsigned int g_bar_count;
__device__ volatile unsigned int g_bar_gen;

// -------- software grid barrier (all NCTA CTAs co-resident) --------
__device__ __forceinline__ void grid_barrier() {
    __syncthreads();
    if (threadIdx.x == 0) {
        __threadfence();   // release all CTA writes (ordered by the syncthreads above)
        unsigned int gen = g_bar_gen;
        unsigned int t = atomicAdd(&g_bar_count, 1u);
        if (t == NCTA - 1) {
            g_bar_count = 0u;
            __threadfence();
            g_bar_gen = gen + 1u;
        } else {
            while (g_bar_gen == gen) { }
            __threadfence();  // acquire
        }
    }
    __syncthreads();
}

// ===================================================================
// Phase A: x_proj[m][g] = sum_d A[m][d] * W[g][d] + bias[g]
// M=16384, N=4096, K=1024. 128x128 tile, 8x8 per thread, BK=16.
// Inner product in packed f32x2 (FFMA2): acc pairs along N.
// ===================================================================
__global__ __launch_bounds__(256, 2) void sgemm_xproj(
    const float* __restrict__ Ain,   // nullptr => use g_hs
    const float* __restrict__ Wl,    // [4096][1024]
    const float* __restrict__ bias)  // [4096]
{
    const float* A = Ain ? Ain : (const float*)g_hs;
    __shared__ float As[16][128];
    __shared__ float Bs[16][128];
    int tid = threadIdx.x;
    int n0 = blockIdx.x * 128;
    int m0 = blockIdx.y * 128;
    int tx = tid & 15, ty = tid >> 4;
    int lrow = tid >> 2;          // 0..63
    int lk = (tid & 3) * 4;       // 0,4,8,12

    unsigned long long acc2[8][4];
#pragma unroll
    for (int i = 0; i < 8; i++)
#pragma unroll
        for (int j = 0; j < 4; j++) acc2[i][j] = 0ull;

    for (int k0 = 0; k0 < 1024; k0 += 16) {
#pragma unroll
        for (int rr = 0; rr < 2; rr++) {
            int row = lrow + rr * 64;
            int m = m0 + row;
            const float* ap = A + (size_t)(m & 15) * 1048576 + (size_t)(m >> 4) * 1024 + k0 + lk;
            float4 av = *(const float4*)ap;
            As[lk + 0][row] = av.x; As[lk + 1][row] = av.y;
            As[lk + 2][row] = av.z; As[lk + 3][row] = av.w;
            const float* wp = Wl + (size_t)(n0 + row) * 1024 + k0 + lk;
            float4 wv = *(const float4*)wp;
            Bs[lk + 0][row] = wv.x; Bs[lk + 1][row] = wv.y;
            Bs[lk + 2][row] = wv.z; Bs[lk + 3][row] = wv.w;
        }
        __syncthreads();
#pragma unroll
        for (int k = 0; k < 16; k++) {
            float a[8];
            *(float4*)&a[0] = *(const float4*)&As[k][ty * 8];
            *(float4*)&a[4] = *(const float4*)&As[k][ty * 8 + 4];
            ulonglong2 b01 = *(const ulonglong2*)&Bs[k][tx * 8];
            ulonglong2 b23 = *(const ulonglong2*)&Bs[k][tx * 8 + 4];
#pragma unroll
            for (int i = 0; i < 8; i++) {
                unsigned long long ap = pack2(a[i]);
                fma2(acc2[i][0], ap, b01.x);
                fma2(acc2[i][1], ap, b01.y);
                fma2(acc2[i][2], ap, b23.x);
                fma2(acc2[i][3], ap, b23.y);
            }
        }
        __syncthreads();
    }

    float bb[8];
#pragma unroll
    for (int j = 0; j < 8; j++) bb[j] = bias[n0 + tx * 8 + j];
#pragma unroll
    for (int i = 0; i < 8; i++) {
        int m = m0 + ty * 8 + i;
        float* cp = g_xproj + (size_t)m * 4096 + n0 + tx * 8;
#pragma unroll
        for (int jp = 0; jp < 4; jp++) {
            float2 v = unpack2(acc2[i][jp]);
            v.x += bb[jp * 2 + 0];
            v.y += bb[jp * 2 + 1];
            *(float2*)(cp + jp * 2) = v;
        }
    }
}

// ===================================================================
// Phase B: persistent sLSTM recurrence, 512 threads (16 warps).
// CTA j owns h-units [8j, 8j+8) => gate rows {g*1024 + 8j + u}.
// R slice (32x1024 fp32) in SMEM; h broadcast via g_hglob.
// Thread = (ksplit 0..15 [64 k each] = warp id, uu 0..7, b-group 0..3).
// acc in f32x2 over batch pairs. Partials buffer aliased onto sH
// (sH is dead between GEMM-end and the next reload).
// SMEM: R 128.5KB + sH 64KB = 197.1 KB -> 1 CTA/SM, 128 CTAs co-resident.
// ===================================================================
__global__ __launch_bounds__(512, 1) void slstm_rec(const float* __restrict__ Rl)
{
    extern __shared__ float smem[];
    float* sRs   = smem;                        // 32 * RS_STRIDE
    float* sH    = smem + 32 * RS_STRIDE;       // [1024][16]
    float* sPart = sH;                          // aliased: [16 ksplit][520]

    int tid = threadIdx.x;
    int u_base = blockIdx.x * 8;

    // stage R slice: local row r = gate*8 + u
    for (int i = tid; i < 32 * 256; i += 512) {
        int r = i >> 8;
        int c4 = (i & 255) * 4;
        int gate = r >> 3, uu2 = r & 7;
        float4 v = *(const float4*)(Rl + (size_t)(gate * 1024 + u_base + uu2) * 1024 + c4);
        float* dst = sRs + r * RS_STRIDE + c4;
        dst[0] = v.x; dst[1] = v.y; dst[2] = v.z; dst[3] = v.w;
    }
    // h0 = 0
    for (int i = tid; i < 16384; i += 512) sH[i] = 0.f;

    // GEMM thread mapping
    int ksplit = tid >> 5;        // == warp id: conflict-free LDS within warp
    int pos = tid & 31;
    int uu = pos >> 2;
    int b0 = (pos & 3) * 4;
    const float* rb0 = sRs + (0 * 8 + uu) * RS_STRIDE + ksplit * 64;
    const float* rb1 = sRs + (1 * 8 + uu) * RS_STRIDE + ksplit * 64;
    const float* rb2 = sRs + (2 * 8 + uu) * RS_STRIDE + ksplit * 64;
    const float* rb3 = sRs + (3 * 8 + uu) * RS_STRIDE + ksplit * 64;
    const float* hb = sH + ksplit * 64 * 16 + b0;

    // pointwise state (threads < 128): (b, u)
    int pu = tid & 7, pb = (tid >> 3) & 15;
    float creg = 0.f, nreg = 1.f, mreg = 0.f;

    __syncthreads();

    for (int t = 0; t < T_STEPS; t++) {
        // prefetch x_proj for this step (latency hides under GEMM)
        float xpre[4];
        if (tid < 128) {
            const float* xp = g_xproj + ((size_t)t * 16 + pb) * 4096 + u_base + pu;
            xpre[0] = __ldg(xp);
            xpre[1] = __ldg(xp + 1024);
            xpre[2] = __ldg(xp + 2048);
            xpre[3] = __ldg(xp + 3072);
        }

        unsigned long long acc2[4][2];
#pragma unroll
        for (int g = 0; g < 4; g++) { acc2[g][0] = 0ull; acc2[g][1] = 0ull; }

#pragma unroll 4
        for (int kk = 0; kk < 64; kk += 4) {
            float4 rv0 = *(const float4*)(rb0 + kk);
            float4 rv1 = *(const float4*)(rb1 + kk);
            float4 rv2 = *(const float4*)(rb2 + kk);
            float4 rv3 = *(const float4*)(rb3 + kk);
            ulonglong2 hv0 = *(const ulonglong2*)(hb + (kk + 0) * 16);
            ulonglong2 hv1 = *(const ulonglong2*)(hb + (kk + 1) * 16);
            ulonglong2 hv2 = *(const ulonglong2*)(hb + (kk + 2) * 16);
            ulonglong2 hv3 = *(const ulonglong2*)(hb + (kk + 3) * 16);
#define DO_G(G, RV) { \
            unsigned long long p0 = pack2(RV.x), p1 = pack2(RV.y); \
            unsigned long long p2 = pack2(RV.z), p3 = pack2(RV.w); \
            fma2(acc2[G][0], p0, hv0.x); fma2(acc2[G][1], p0, hv0.y); \
            fma2(acc2[G][0], p1, hv1.x); fma2(acc2[G][1], p1, hv1.y); \
            fma2(acc2[G][0], p2, hv2.x); fma2(acc2[G][1], p2, hv2.y); \
            fma2(acc2[G][0], p3, hv3.x); fma2(acc2[G][1], p3, hv3.y); }
            DO_G(0, rv0) DO_G(1, rv1) DO_G(2, rv2) DO_G(3, rv3)
#undef DO_G
        }

        __syncthreads();   // all sH reads done before aliased partial writes

#pragma unroll
        for (int g = 0; g < 4; g++) {
            int row = g * 8 + uu;
#pragma unroll
            for (int bp = 0; bp < 2; bp++) {
                float2 v = unpack2(acc2[g][bp]);
                *(float2*)(sPart + ksplit * 520 + row * 16 + b0 + bp * 2) = v;
            }
        }
        __syncthreads();

        if (tid < 128) {
            float pre[4];
#pragma unroll
            for (int g = 0; g < 4; g++) {
                float s = xpre[g];
                int base = (g * 8 + pu) * 16 + pb;
#pragma unroll
                for (int ks = 0; ks < 16; ks++) s += sPart[ks * 520 + base];
                pre[g] = s;
            }
            float z = tanhf(pre[0]);
            float o = 1.f / (1.f + expf(-pre[3]));
            float mn = fmaxf(pre[2] + mreg, pre[1]);
            float ip = expf(pre[1] - mn);
            float fp = expf(pre[2] + mreg - mn);
            creg = fp * creg + ip * z;
            nreg = fp * nreg + ip;
            mreg = mn;
            float h = o * (creg / nreg);
            g_hglob[(u_base + pu) * 16 + pb] = h;
            g_hs[(size_t)pb * 1048576 + (size_t)t * 1024 + u_base + pu] = h;
        }

        if (t + 1 < T_STEPS) {
            grid_barrier();
            // reload h_{t-1} broadcast from global into SMEM
            for (int i = tid * 4; i < 16384; i += 2048) {
                float4 v = *(const float4*)(g_hglob + i);
                *(float4*)(sH + i) = v;
            }
            __syncthreads();
        }
    }
}

// ===================================================================
// Final: out[b][o] = sum_k h_last[b][k] * Wout[o][k] + bout[o]
// ===================================================================
__global__ __launch_bounds__(256) void final_out(
    const float* __restrict__ Wout, const float* __restrict__ bout,
    float* __restrict__ out)
{
    int o = (blockIdx.x * blockDim.x + threadIdx.x) >> 5;
    int lane = threadIdx.x & 31;
    const float* wr = Wout + (size_t)o * 1024;
    float acc[16];
#pragma unroll
    for (int b = 0; b < 16; b++) acc[b] = 0.f;
    for (int k = lane; k < 1024; k += 32) {
        float w = wr[k];
        const float4* hp = (const float4*)(g_hglob + k * 16);
        float4 h0 = hp[0], h1 = hp[1], h2 = hp[2], h3 = hp[3];
        acc[0]  += w * h0.x; acc[1]  += w * h0.y; acc[2]  += w * h0.z; acc[3]  += w * h0.w;
        acc[4]  += w * h1.x; acc[5]  += w * h1.y; acc[6]  += w * h1.z; acc[7]  += w * h1.w;
        acc[8]  += w * h2.x; acc[9]  += w * h2.y; acc[10] += w * h2.z; acc[11] += w * h2.w;
        acc[12] += w * h3.x; acc[13] += w * h3.y; acc[14] += w * h3.z; acc[15] += w * h3.w;
    }
#pragma unroll
    for (int b = 0; b < 16; b++) {
#pragma unroll
        for (int off = 16; off; off >>= 1)
            acc[b] += __shfl_down_sync(0xffffffffu, acc[b], off);
    }
    if (lane == 0) {
        float bo = bout[o];
#pragma unroll
        for (int b = 0; b < 16; b++)
            out[(size_t)b * 1024 + o] = acc[b] + bo;
    }
}

// ===================================================================
extern "C" void kernel_launch(void* const* d_in, const int* in_sizes, int n_in,
                              void* d_out, int out_size)
{
    const float* x    = (const float*)d_in[0];  // [16][1024][1024]
    const float* W    = (const float*)d_in[1];  // [2][4096][1024]
    const float* R    = (const float*)d_in[2];  // [2][4096][1024]
    const float* bias = (const float*)d_in[3];  // [2][4096]
    const float* Wout = (const float*)d_in[4];  // [1024][1024]
    const float* bout = (const float*)d_in[5];  // [1024]
    float* out = (float*)d_out;                 // [16][1024]

    const int REC_SMEM = (32 * RS_STRIDE + 16384) * 4;  // 197120 B
    cudaFuncSetAttribute(slstm_rec, cudaFuncAttributeMaxDynamicSharedMemorySize, REC_SMEM);

    dim3 ggrid(32, 128);
    // layer 0
    sgemm_xproj<<<ggrid, 256>>>(x, W, bias);
    slstm_rec<<<NCTA, 512, REC_SMEM>>>(R);
    // layer 1
    sgemm_xproj<<<ggrid, 256>>>(nullptr, W + (size_t)4096 * 1024, bias + 4096);
    slstm_rec<<<NCTA, 512, REC_SMEM>>>(R + (size_t)4096 * 1024);
    // output projection
    final_out<<<128, 256>>>(Wout, bout, out);
}